// round 15
// baseline (speedup 1.0000x reference)
#include <cuda_runtime.h>
#include <cuda_fp16.h>
#include <cstdint>
#include <cstddef>

#define NN 8
#define CC 256
#define HH 64
#define WW 64
#define LL (HH*WW)      // 4096
#define GG 8
#define KK 9
#define OMC (GG*KK*3)   // 216

// Scratch (allocation-free: __device__ globals)
__device__ __half g_x_h  [(size_t)NN*CC*LL];  // (n, C, L)  fp16 copy of x
__device__ __half g_value[(size_t)NN*LL*CC];  // (n, L, C)  fp16
__device__ __half g_omin [(size_t)NN*CC*LL];  // (n, C, L)  fp16 depthwise out
__device__ float  g_om   [(size_t)NN*LL*OMC]; // (n, L, 216)
__device__ __half g_samp [(size_t)NN*LL*CC];  // (n, L, C)  fp16
__device__ __half g_vpw_h[CC*CC];             // pre-halved weights
__device__ __half g_omw_h[OMC*CC];
__device__ __half g_opw_h[CC*CC];

// ---------------------------------------------------------------------------
// helpers
// ---------------------------------------------------------------------------
__device__ __forceinline__ uint32_t f2h2(float lo, float hi) {
    __half2 h = __floats2half2_rn(lo, hi);
    return *(uint32_t*)&h;
}
__device__ __forceinline__ void ldsm4(uint32_t addr, uint32_t& r0, uint32_t& r1,
                                      uint32_t& r2, uint32_t& r3) {
    asm volatile("ldmatrix.sync.aligned.m8n8.x4.shared.b16 {%0,%1,%2,%3}, [%4];"
                 : "=r"(r0), "=r"(r1), "=r"(r2), "=r"(r3) : "r"(addr));
}
__device__ __forceinline__ void ldsm4t(uint32_t addr, uint32_t& r0, uint32_t& r1,
                                       uint32_t& r2, uint32_t& r3) {
    asm volatile("ldmatrix.sync.aligned.m8n8.x4.trans.shared.b16 {%0,%1,%2,%3}, [%4];"
                 : "=r"(r0), "=r"(r1), "=r"(r2), "=r"(r3) : "r"(addr));
}
__device__ __forceinline__ void mma16(float* d, const uint32_t* a, const uint32_t* b) {
    asm volatile("mma.sync.aligned.m16n8k16.row.col.f32.f16.f16.f32 "
                 "{%0,%1,%2,%3}, {%4,%5,%6,%7}, {%8,%9}, {%0,%1,%2,%3};"
                 : "+f"(d[0]), "+f"(d[1]), "+f"(d[2]), "+f"(d[3])
                 : "r"(a[0]), "r"(a[1]), "r"(a[2]), "r"(a[3]),
                   "r"(b[0]), "r"(b[1]));
}
__device__ __forceinline__ void cp16(uint32_t dst, const void* src) {
    asm volatile("cp.async.cg.shared.global [%0], [%1], 16;" :: "r"(dst), "l"(src));
}
__device__ __forceinline__ void cp8(uint32_t dst, const void* src) {
    asm volatile("cp.async.ca.shared.global [%0], [%1], 8;" :: "r"(dst), "l"(src));
}
#define CP_COMMIT() asm volatile("cp.async.commit_group;" ::: "memory")
#define CP_WAIT1()  asm volatile("cp.async.wait_group 1;" ::: "memory")

// ---------------------------------------------------------------------------
// Prep: pre-halve weights
// ---------------------------------------------------------------------------
__global__ void __launch_bounds__(256)
prep_w(const float* __restrict__ vpw, const float* __restrict__ omw,
       const float* __restrict__ opw)
{
    int t = blockIdx.x * 256 + threadIdx.x;
    if (t < CC * CC)  g_vpw_h[t] = __float2half(vpw[t]);
    if (t < OMC * CC) g_omw_h[t] = __float2half(omw[t]);
    if (t < CC * CC)  g_opw_h[t] = __float2half(opw[t]);
}

// ---------------------------------------------------------------------------
// Fused: depthwise 3x3 conv (fp16 out) + fp16 copy of x.
// One thread = 4 consecutive x pixels of one (n,c,row).
// ---------------------------------------------------------------------------
__global__ void __launch_bounds__(256)
dwx_fused(const float* __restrict__ x, const float* __restrict__ w,
          const float* __restrict__ b)
{
    int t = blockIdx.x * blockDim.x + threadIdx.x;
    if (t >= NN * CC * HH * (WW / 4)) return;
    int x4 = (t & 15) * 4;
    int yy = (t >> 4) & (HH - 1);
    int c  = (t >> 10) & (CC - 1);
    int n  = t >> 18;

    const float* base = x + ((size_t)(n * CC + c) * HH) * WW;
    float wc[9];
    #pragma unroll
    for (int i = 0; i < 9; i++) wc[i] = w[c * 9 + i];

    float v[3][6];
    #pragma unroll
    for (int dy = 0; dy < 3; dy++) {
        int row = yy + dy - 1;
        if (row >= 0 && row < HH) {
            const float* rp = base + row * WW + x4;
            v[dy][0] = (x4 > 0) ? rp[-1] : 0.f;
            float4 m = *(const float4*)rp;
            v[dy][1] = m.x; v[dy][2] = m.y; v[dy][3] = m.z; v[dy][4] = m.w;
            v[dy][5] = (x4 + 4 < WW) ? rp[4] : 0.f;
        } else {
            #pragma unroll
            for (int i = 0; i < 6; i++) v[dy][i] = 0.f;
        }
    }

    const size_t lin = (size_t)((n * CC + c) * HH + yy) * WW + x4;

    // fp16 copy of x (center row)
    uint2 xh = make_uint2(f2h2(v[1][1], v[1][2]), f2h2(v[1][3], v[1][4]));
    *(uint2*)(g_x_h + lin) = xh;

    // depthwise conv
    float bc = b[c];
    float o[4];
    #pragma unroll
    for (int i = 0; i < 4; i++) {
        float s = bc;
        #pragma unroll
        for (int dy = 0; dy < 3; dy++)
            #pragma unroll
            for (int dx = 0; dx < 3; dx++)
                s = fmaf(v[dy][i + dx], wc[dy * 3 + dx], s);
        o[i] = s;
    }
    uint2 oh = make_uint2(f2h2(o[0], o[1]), f2h2(o[2], o[3]));
    *(uint2*)(g_omin + lin) = oh;
}

// ---------------------------------------------------------------------------
// fp16 tensor-core batched GEMM, BM=128, BN=64, BK=16, fp32 accumulate,
// 3-stage cp.async pipeline. 8 warps = 4(m) x 2(n), 32x32 warp tiles ->
// 32 accumulators/thread (~75 regs -> 3 blocks/SM without caps).
//   out[m][j] = sum_k a(m,k)*Bw[j*Kc+k] (+bias)
//   A_COL : a(m,k) = A[k*M + m], staged natural [k][m] (ATS=136 halves),
//           consumed via ldmatrix.x4.trans. cp16 per thread.
//   !A_COL: a(m,k) = A[m*Kc + k], [m][k] rows of PADH=40, 2 x cp8/thread.
//   B: one cp8/thread (64 rows x 16 k), rows index-clamped for Nj<BN tail.
// ---------------------------------------------------------------------------
template<bool A_COL, bool OUT_T, bool HAS_BIAS, typename TO>
__global__ void __launch_bounds__(256)
gemm_hp(const __half* __restrict__ A, const __half* __restrict__ Bw,
        const float* __restrict__ bias, TO* __restrict__ out,
        int M, int Nj, int Kc)
{
    constexpr int NSTAGE = 3;
    constexpr int BM = 128, BN = 64, BK = 16, PADH = 40;
    constexpr int ATS = 136;                 // A-trans row stride in halves
    __shared__ __half As[NSTAGE][BM * PADH]; // A_COL uses [16][136] region
    __shared__ __half Bs[NSTAGE][BN * PADH];

    const int tid = threadIdx.x;
    const int bz = blockIdx.z;
    A   += (size_t)bz * M * Kc;
    out += (size_t)bz * M * Nj;
    const int m0 = blockIdx.y * BM;
    const int j0 = blockIdx.x * BN;

    // ---- staging setup ----
    // A_COL: one 16B chunk/thread: (s_k, 8 consecutive m)
    const int s_k = tid >> 4;
    const int s_m = (tid & 15) * 8;
    const __half* at_ptr = A + (size_t)s_k * M + m0 + s_m;
    // !A_COL: two 8B chunks/thread: (row m, 4 k)
    int a_m[2], a_k[2];
    const __half* a_ptr[2];
    #pragma unroll
    for (int p = 0; p < 2; p++) {
        int lin = (tid + p * 256) * 4;
        if (!A_COL) {
            a_k[p] = lin & 15;  a_m[p] = lin >> 4;
            a_ptr[p] = A + (size_t)(m0 + a_m[p]) * Kc + a_k[p];
        }
    }
    // B: one 8B chunk/thread: (row j clamped, 4 k)
    const int sb_j = tid >> 2;          // 0..63
    const int sb_k = (tid & 3) * 4;     // 0,4,8,12
    int jrow = j0 + sb_j;
    if (jrow >= Nj) jrow = Nj - 1;      // clamp: cols >= Nj never written
    const __half* b_ptr = Bw + (size_t)jrow * Kc + sb_k;

    // ---- compute-side lane addresses ----
    const int lane = tid & 31, wrp = tid >> 5;
    const int wm = wrp & 3, wn = wrp >> 2;      // 4 m-warps x 2 n-warps
    const uint32_t as_base = (uint32_t)__cvta_generic_to_shared(&As[0][0]);
    const uint32_t bs_base = (uint32_t)__cvta_generic_to_shared(&Bs[0][0]);
    const uint32_t ABUFB = BM * PADH * 2;       // 10240 B per stage
    const uint32_t BBUFB = BN * PADH * 2;       // 5120 B per stage

    // staging smem dst addresses (stage 0)
    const uint32_t asw = as_base + (uint32_t)(s_k * ATS + s_m) * 2;   // A_COL
    uint32_t aswp[2];
    #pragma unroll
    for (int p = 0; p < 2; p++)
        if (!A_COL) aswp[p] = as_base + (uint32_t)(a_m[p] * PADH + a_k[p]) * 2;
    const uint32_t bsw = bs_base + (uint32_t)(sb_j * PADH + sb_k) * 2;

    uint32_t aaddr0;
    if (A_COL) {
        int krow = (lane & 7) + 8 * (lane >> 4);
        int col  = wm * 32 + 8 * ((lane >> 3) & 1);
        aaddr0 = as_base + (uint32_t)(krow * ATS + col) * 2;
    } else {
        int arow_l = wm * 32 + (lane & 7) + 8 * ((lane >> 3) & 1);
        int acol_b = 16 * (lane >> 4);
        aaddr0 = as_base + (uint32_t)(arow_l * (PADH * 2) + acol_b);
    }
    const int brow_l = wn * 32 + (lane & 7) + 8 * (lane >> 4);
    const int bcol_b = 16 * ((lane >> 3) & 1);
    const uint32_t baddr0 = bs_base + (uint32_t)(brow_l * (PADH * 2) + bcol_b);

    float acc[2][4][4];
    #pragma unroll
    for (int mi = 0; mi < 2; mi++)
        #pragma unroll
        for (int nj = 0; nj < 4; nj++)
            #pragma unroll
            for (int q = 0; q < 4; q++) acc[mi][nj][q] = 0.f;

    const int KT = Kc / BK;

    auto issue_stage = [&](int st, int kt) {
        if (A_COL) {
            cp16(asw + st * ABUFB, at_ptr + (size_t)kt * BK * M);
        } else {
            #pragma unroll
            for (int p = 0; p < 2; p++)
                cp8(aswp[p] + st * ABUFB, a_ptr[p] + kt * BK);
        }
        cp8(bsw + st * BBUFB, b_ptr + kt * BK);
    };

    auto compute = [&](int buf) {
        const uint32_t abase = aaddr0 + buf * ABUFB;
        const uint32_t bbase = baddr0 + buf * BBUFB;
        uint32_t a[2][4], b[4][2];
        #pragma unroll
        for (int mi = 0; mi < 2; mi++) {
            if (A_COL)
                ldsm4t(abase + (uint32_t)(mi * 16 * 2),
                       a[mi][0], a[mi][1], a[mi][2], a[mi][3]);
            else
                ldsm4(abase + (uint32_t)(mi * 16 * PADH * 2),
                      a[mi][0], a[mi][1], a[mi][2], a[mi][3]);
        }
        #pragma unroll
        for (int njp = 0; njp < 2; njp++)
            ldsm4(bbase + (uint32_t)(njp * 16 * PADH * 2),
                  b[2 * njp][0], b[2 * njp][1], b[2 * njp + 1][0], b[2 * njp + 1][1]);
        #pragma unroll
        for (int mi = 0; mi < 2; mi++)
            #pragma unroll
            for (int nj = 0; nj < 4; nj++)
                mma16(acc[mi][nj], a[mi], b[nj]);
    };

    // ---- 3-stage pipeline ----
    issue_stage(0, 0);
    CP_COMMIT();
    if (KT > 1) issue_stage(1, 1);
    CP_COMMIT();
    CP_WAIT1();
    __syncthreads();

    for (int kt = 0; kt < KT; kt++) {
        compute(kt % 3);
        if (kt + 2 < KT) issue_stage((kt + 2) % 3, kt + 2);
        CP_COMMIT();
        CP_WAIT1();
        __syncthreads();
    }

    // ---- epilogue ----
    const int r = lane >> 2, c = lane & 3;
    #pragma unroll
    for (int mi = 0; mi < 2; mi++) {
        int m = m0 + wm * 32 + mi * 16 + r;
        #pragma unroll
        for (int nj = 0; nj < 4; nj++) {
            int j = j0 + wn * 32 + nj * 8 + 2 * c;
            if (j < Nj) {
                float bj0 = HAS_BIAS ? bias[j]     : 0.f;
                float bj1 = HAS_BIAS ? bias[j + 1] : 0.f;
                float v0 = acc[mi][nj][0] + bj0;
                float v1 = acc[mi][nj][1] + bj1;
                float v2 = acc[mi][nj][2] + bj0;
                float v3 = acc[mi][nj][3] + bj1;
                if (OUT_T) {
                    ((float*)out)[(size_t)j * M + m]           = v0;
                    ((float*)out)[(size_t)(j + 1) * M + m]     = v1;
                    ((float*)out)[(size_t)j * M + m + 8]       = v2;
                    ((float*)out)[(size_t)(j + 1) * M + m + 8] = v3;
                } else if (sizeof(TO) == 2) {
                    *(uint32_t*)((__half*)out + (size_t)m * Nj + j)       = f2h2(v0, v1);
                    *(uint32_t*)((__half*)out + (size_t)(m + 8) * Nj + j) = f2h2(v2, v3);
                } else {
                    *(float2*)((float*)out + (size_t)m * Nj + j)       = make_float2(v0, v1);
                    *(float2*)((float*)out + (size_t)(m + 8) * Nj + j) = make_float2(v2, v3);
                }
            }
        }
    }
}

// ---------------------------------------------------------------------------
// Deformable bilinear sampling, fp16 value: one thread = (n, l, g, c8),
// 8 channels per thread (uint4 = 8 halves = 16B per corner load).
// ---------------------------------------------------------------------------
__global__ void __launch_bounds__(256)
samp_h8(const __half* __restrict__ value, const float* __restrict__ om,
        __half* __restrict__ sampled)
{
    int t = blockIdx.x * blockDim.x + threadIdx.x;
    if (t >= NN * LL * GG * 4) return;
    int c8 = (t & 3) * 8;
    int g  = (t >> 2) & (GG - 1);
    int nl = t >> 5;
    int l  = nl & (LL - 1);
    int n  = nl >> 12;
    int yy = l >> 6, xx = l & 63;

    const float*  omp = om + nl * OMC + g * 27;
    const __half* vb  = value + (size_t)n * (LL * CC) + g * 32 + c8;

    float a0 = 0.f, a1 = 0.f, a2 = 0.f, a3 = 0.f;
    float a4 = 0.f, a5 = 0.f, a6 = 0.f, a7 = 0.f;

    #pragma unroll
    for (int k = 0; k < KK; k++) {
        float offy = omp[2 * k];
        float offx = omp[2 * k + 1];
        float msk  = omp[18 + k];
        float py = (float)(yy + k / 3 - 1) + offy;
        float px = (float)(xx + k % 3 - 1) + offx;
        float fy = floorf(py), fx = floorf(px);
        float tyf = py - fy, txf = px - fx;
        int y0 = (int)fy, x0 = (int)fx;

        bool yv0 = (unsigned)y0 < HH;
        bool yv1 = (unsigned)(y0 + 1) < HH;
        bool xv0 = (unsigned)x0 < WW;
        bool xv1 = (unsigned)(x0 + 1) < WW;

        float wy0 = 1.f - tyf, wx0 = 1.f - txf;
        float w00 = msk * wy0 * wx0;
        float w01 = msk * wy0 * txf;
        float w10 = msk * tyf * wx0;
        float w11 = msk * tyf * txf;

        const __half* p = vb + (y0 * WW + x0) * CC;

        #pragma unroll
        for (int cr = 0; cr < 4; cr++) {
            bool ok; const __half* cp; float w;
            if (cr == 0)      { ok = yv0 && xv0; cp = p;                w = w00; }
            else if (cr == 1) { ok = yv0 && xv1; cp = p + CC;           w = w01; }
            else if (cr == 2) { ok = yv1 && xv0; cp = p + WW * CC;      w = w10; }
            else              { ok = yv1 && xv1; cp = p + WW * CC + CC; w = w11; }
            if (ok) {
                uint4 v = *(const uint4*)cp;
                float2 f0 = __half22float2(*(__half2*)&v.x);
                float2 f1 = __half22float2(*(__half2*)&v.y);
                float2 f2 = __half22float2(*(__half2*)&v.z);
                float2 f3 = __half22float2(*(__half2*)&v.w);
                a0 = fmaf(w, f0.x, a0); a1 = fmaf(w, f0.y, a1);
                a2 = fmaf(w, f1.x, a2); a3 = fmaf(w, f1.y, a3);
                a4 = fmaf(w, f2.x, a4); a5 = fmaf(w, f2.y, a5);
                a6 = fmaf(w, f3.x, a6); a7 = fmaf(w, f3.y, a7);
            }
        }
    }

    uint4 o;
    o.x = f2h2(a0, a1); o.y = f2h2(a2, a3);
    o.z = f2h2(a4, a5); o.w = f2h2(a6, a7);
    *(uint4*)(sampled + (size_t)nl * CC + g * 32 + c8) = o;
}

// ---------------------------------------------------------------------------
extern "C" void kernel_launch(void* const* d_in, const int* in_sizes, int n_in,
                              void* d_out, int out_size)
{
    const float* x   = (const float*)d_in[0];
    const float* dww = (const float*)d_in[1];
    const float* dwb = (const float*)d_in[2];
    const float* omw = (const float*)d_in[3];
    const float* omb = (const float*)d_in[4];
    const float* vpw = (const float*)d_in[5];
    const float* vpb = (const float*)d_in[6];
    const float* opw = (const float*)d_in[7];
    float* out = (float*)d_out;

    __half *pxh, *pval, *pomin, *psamp, *pvpw, *pomw, *popw;
    float *pom;
    cudaGetSymbolAddress((void**)&pxh,   g_x_h);
    cudaGetSymbolAddress((void**)&pval,  g_value);
    cudaGetSymbolAddress((void**)&pomin, g_omin);
    cudaGetSymbolAddress((void**)&pom,   g_om);
    cudaGetSymbolAddress((void**)&psamp, g_samp);
    cudaGetSymbolAddress((void**)&pvpw,  g_vpw_h);
    cudaGetSymbolAddress((void**)&pomw,  g_omw_h);
    cudaGetSymbolAddress((void**)&popw,  g_opw_h);

    // 0) pre-halve weights; fused dw conv + x fp16 copy
    prep_w<<<(CC * CC + 255) / 256, 256>>>(vpw, omw, opw);
    dwx_fused<<<(NN * CC * HH * (WW / 4) + 255) / 256, 256>>>(x, dww, dwb);

    // 1) value projection: (n,C,L) x_h -> value (n,L,C) fp16
    gemm_hp<true, false, true, __half>
        <<<dim3(CC / 64, LL / 128, NN), 256>>>(pxh, pvpw, vpb, pval, LL, CC, CC);

    // 2) offset/mask projection: om_in -> om (n,L,216) fp32
    gemm_hp<true, false, true, float>
        <<<dim3((OMC + 63) / 64, LL / 128, NN), 256>>>(pomin, pomw, omb, pom, LL, OMC, CC);

    // 3) deformable sampling -> sampled (n,L,C) fp16
    samp_h8<<<(NN * LL * GG * 4 + 255) / 256, 256>>>(pval, pom, psamp);

    // 4) output projection (half A), write transposed directly to d_out (n,C,H,W)
    gemm_hp<false, true, false, float>
        <<<dim3(CC / 64, LL / 128, NN), 256>>>(psamp, popw, nullptr, out, LL, CC, CC);
}

// round 16
// speedup vs baseline: 1.0452x; 1.0452x over previous
#include <cuda_runtime.h>
#include <cuda_fp16.h>
#include <cstdint>
#include <cstddef>

#define NN 8
#define CC 256
#define HH 64
#define WW 64
#define LL (HH*WW)      // 4096
#define GG 8
#define KK 9
#define OMC (GG*KK*3)   // 216

// Scratch (allocation-free: __device__ globals)
__device__ __half g_x_h  [(size_t)NN*CC*LL];  // (n, C, L)  fp16 copy of x
__device__ __half g_value[(size_t)NN*LL*CC];  // (n, L, C)  fp16
__device__ __half g_omin [(size_t)NN*CC*LL];  // (n, C, L)  fp16 depthwise out
__device__ float  g_om   [(size_t)NN*LL*OMC]; // (n, L, 216)
__device__ __half g_samp [(size_t)NN*LL*CC];  // (n, L, C)  fp16
__device__ __half g_vpw_h[CC*CC];             // pre-halved weights
__device__ __half g_omw_h[OMC*CC];
__device__ __half g_opw_h[CC*CC];

// ---------------------------------------------------------------------------
// helpers
// ---------------------------------------------------------------------------
__device__ __forceinline__ uint32_t f2h2(float lo, float hi) {
    __half2 h = __floats2half2_rn(lo, hi);
    return *(uint32_t*)&h;
}
__device__ __forceinline__ void ldsm4(uint32_t addr, uint32_t& r0, uint32_t& r1,
                                      uint32_t& r2, uint32_t& r3) {
    asm volatile("ldmatrix.sync.aligned.m8n8.x4.shared.b16 {%0,%1,%2,%3}, [%4];"
                 : "=r"(r0), "=r"(r1), "=r"(r2), "=r"(r3) : "r"(addr));
}
__device__ __forceinline__ void ldsm4t(uint32_t addr, uint32_t& r0, uint32_t& r1,
                                       uint32_t& r2, uint32_t& r3) {
    asm volatile("ldmatrix.sync.aligned.m8n8.x4.trans.shared.b16 {%0,%1,%2,%3}, [%4];"
                 : "=r"(r0), "=r"(r1), "=r"(r2), "=r"(r3) : "r"(addr));
}
__device__ __forceinline__ void mma16(float* d, const uint32_t* a, const uint32_t* b) {
    asm volatile("mma.sync.aligned.m16n8k16.row.col.f32.f16.f16.f32 "
                 "{%0,%1,%2,%3}, {%4,%5,%6,%7}, {%8,%9}, {%0,%1,%2,%3};"
                 : "+f"(d[0]), "+f"(d[1]), "+f"(d[2]), "+f"(d[3])
                 : "r"(a[0]), "r"(a[1]), "r"(a[2]), "r"(a[3]),
                   "r"(b[0]), "r"(b[1]));
}
__device__ __forceinline__ void cp16(uint32_t dst, const void* src) {
    asm volatile("cp.async.cg.shared.global [%0], [%1], 16;" :: "r"(dst), "l"(src));
}
__device__ __forceinline__ void cp8(uint32_t dst, const void* src) {
    asm volatile("cp.async.ca.shared.global [%0], [%1], 8;" :: "r"(dst), "l"(src));
}
#define CP_COMMIT() asm volatile("cp.async.commit_group;" ::: "memory")
#define CP_WAIT1()  asm volatile("cp.async.wait_group 1;" ::: "memory")

// ---------------------------------------------------------------------------
// Prep: pre-halve weights
// ---------------------------------------------------------------------------
__global__ void __launch_bounds__(256)
prep_w(const float* __restrict__ vpw, const float* __restrict__ omw,
       const float* __restrict__ opw)
{
    int t = blockIdx.x * 256 + threadIdx.x;
    if (t < CC * CC)  g_vpw_h[t] = __float2half(vpw[t]);
    if (t < OMC * CC) g_omw_h[t] = __float2half(omw[t]);
    if (t < CC * CC)  g_opw_h[t] = __float2half(opw[t]);
}

// ---------------------------------------------------------------------------
// Fused: depthwise 3x3 conv (fp16 out) + fp16 copy of x.
// One thread = 4 consecutive x pixels of one (n,c,row).
// ---------------------------------------------------------------------------
__global__ void __launch_bounds__(256)
dwx_fused(const float* __restrict__ x, const float* __restrict__ w,
          const float* __restrict__ b)
{
    int t = blockIdx.x * blockDim.x + threadIdx.x;
    if (t >= NN * CC * HH * (WW / 4)) return;
    int x4 = (t & 15) * 4;
    int yy = (t >> 4) & (HH - 1);
    int c  = (t >> 10) & (CC - 1);
    int n  = t >> 18;

    const float* base = x + ((size_t)(n * CC + c) * HH) * WW;
    float wc[9];
    #pragma unroll
    for (int i = 0; i < 9; i++) wc[i] = w[c * 9 + i];

    float v[3][6];
    #pragma unroll
    for (int dy = 0; dy < 3; dy++) {
        int row = yy + dy - 1;
        if (row >= 0 && row < HH) {
            const float* rp = base + row * WW + x4;
            v[dy][0] = (x4 > 0) ? rp[-1] : 0.f;
            float4 m = *(const float4*)rp;
            v[dy][1] = m.x; v[dy][2] = m.y; v[dy][3] = m.z; v[dy][4] = m.w;
            v[dy][5] = (x4 + 4 < WW) ? rp[4] : 0.f;
        } else {
            #pragma unroll
            for (int i = 0; i < 6; i++) v[dy][i] = 0.f;
        }
    }

    const size_t lin = (size_t)((n * CC + c) * HH + yy) * WW + x4;

    // fp16 copy of x (center row)
    uint2 xh = make_uint2(f2h2(v[1][1], v[1][2]), f2h2(v[1][3], v[1][4]));
    *(uint2*)(g_x_h + lin) = xh;

    // depthwise conv
    float bc = b[c];
    float o[4];
    #pragma unroll
    for (int i = 0; i < 4; i++) {
        float s = bc;
        #pragma unroll
        for (int dy = 0; dy < 3; dy++)
            #pragma unroll
            for (int dx = 0; dx < 3; dx++)
                s = fmaf(v[dy][i + dx], wc[dy * 3 + dx], s);
        o[i] = s;
    }
    uint2 oh = make_uint2(f2h2(o[0], o[1]), f2h2(o[2], o[3]));
    *(uint2*)(g_omin + lin) = oh;
}

// ---------------------------------------------------------------------------
// fp16 tensor-core batched GEMM, BM=BN=128, BK=16, fp32 accumulate,
// 3-stage cp.async pipeline (R12/R14-proven configuration):
//   out[m][j] = sum_k a(m,k)*Bw[j*Kc+k] (+bias)
//   A_COL : a(m,k) = A[k*M + m], staged natural [k][m] (ATS=136 halves),
//           consumed via ldmatrix.x4.trans. cp16 per thread.
//   !A_COL: a(m,k) = A[m*Kc + k], [m][k] rows of PADH=40, non-trans.
// B rows index-clamped for Nj<BN (clamped cols never written).
// ---------------------------------------------------------------------------
template<bool A_COL, bool OUT_T, bool HAS_BIAS, typename TO>
__global__ void __launch_bounds__(256)
gemm_hp(const __half* __restrict__ A, const __half* __restrict__ Bw,
        const float* __restrict__ bias, TO* __restrict__ out,
        int M, int Nj, int Kc)
{
    constexpr int NSTAGE = 3;
    constexpr int BM = 128, BN = 128, BK = 16, PADH = 40;
    constexpr int ATS = 136;                 // A-trans row stride in halves
    __shared__ __half As[NSTAGE][BM * PADH]; // A_COL uses [16][136] region
    __shared__ __half Bs[NSTAGE][BM * PADH];

    const int tid = threadIdx.x;
    const int bz = blockIdx.z;
    A   += (size_t)bz * M * Kc;
    out += (size_t)bz * M * Nj;
    const int m0 = blockIdx.y * BM;
    const int j0 = blockIdx.x * BN;

    // ---- staging setup ----
    // A_COL: one 16B chunk/thread: (s_k, 8 consecutive m)
    const int s_k = tid >> 4;
    const int s_m = (tid & 15) * 8;
    const __half* at_ptr = A + (size_t)s_k * M + m0 + s_m;
    // !A_COL: two 8B chunks/thread: (row m, 4 k)
    int a_m[2], a_k[2];
    const __half* a_ptr[2];
    // B: two 8B chunks/thread: (row j clamped, 4 k)
    int b_j[2], b_k[2];
    const __half* b_ptr[2];
    #pragma unroll
    for (int p = 0; p < 2; p++) {
        int lin = (tid + p * 256) * 4;
        if (!A_COL) {
            a_k[p] = lin & 15;  a_m[p] = lin >> 4;
            a_ptr[p] = A + (size_t)(m0 + a_m[p]) * Kc + a_k[p];
        }
        b_k[p] = lin & 15; b_j[p] = lin >> 4;
        int jrow = j0 + b_j[p];
        if (jrow >= Nj) jrow = Nj - 1;      // clamp: cols >= Nj never written
        b_ptr[p] = Bw + (size_t)jrow * Kc + b_k[p];
    }

    // ---- compute-side lane addresses ----
    const int lane = tid & 31, wrp = tid >> 5;
    const int wm = wrp & 1, wn = wrp >> 1;
    const uint32_t as_base = (uint32_t)__cvta_generic_to_shared(&As[0][0]);
    const uint32_t bs_base = (uint32_t)__cvta_generic_to_shared(&Bs[0][0]);
    const uint32_t BUFB = BM * PADH * 2;     // per-stage stride (10240 B)

    // staging smem dst addresses (stage 0)
    const uint32_t asw = as_base + (uint32_t)(s_k * ATS + s_m) * 2;   // A_COL
    uint32_t aswp[2], bsw[2];
    #pragma unroll
    for (int p = 0; p < 2; p++) {
        if (!A_COL) aswp[p] = as_base + (uint32_t)(a_m[p] * PADH + a_k[p]) * 2;
        bsw[p] = bs_base + (uint32_t)(b_j[p] * PADH + b_k[p]) * 2;
    }

    uint32_t aaddr0;
    if (A_COL) {
        int krow = (lane & 7) + 8 * (lane >> 4);
        int col  = wm * 64 + 8 * ((lane >> 3) & 1);
        aaddr0 = as_base + (uint32_t)(krow * ATS + col) * 2;
    } else {
        int arow_l = wm * 64 + (lane & 7) + 8 * ((lane >> 3) & 1);
        int acol_b = 16 * (lane >> 4);
        aaddr0 = as_base + (uint32_t)(arow_l * (PADH * 2) + acol_b);
    }
    const int brow_l = wn * 32 + (lane & 7) + 8 * (lane >> 4);
    const int bcol_b = 16 * ((lane >> 3) & 1);
    const uint32_t baddr0 = bs_base + (uint32_t)(brow_l * (PADH * 2) + bcol_b);

    float acc[4][4][4];
    #pragma unroll
    for (int mi = 0; mi < 4; mi++)
        #pragma unroll
        for (int nj = 0; nj < 4; nj++)
            #pragma unroll
            for (int q = 0; q < 4; q++) acc[mi][nj][q] = 0.f;

    const int KT = Kc / BK;

    auto issue_stage = [&](int st, int kt) {
        uint32_t off = st * BUFB;
        if (A_COL) {
            cp16(asw + off, at_ptr + (size_t)kt * BK * M);
        } else {
            #pragma unroll
            for (int p = 0; p < 2; p++)
                cp8(aswp[p] + off, a_ptr[p] + kt * BK);
        }
        #pragma unroll
        for (int p = 0; p < 2; p++)
            cp8(bsw[p] + off, b_ptr[p] + kt * BK);
    };

    auto compute = [&](int buf) {
        const uint32_t abase = aaddr0 + buf * BUFB;
        const uint32_t bbase = baddr0 + buf * BUFB;
        uint32_t a[4][4], b[4][2];
        #pragma unroll
        for (int mi = 0; mi < 4; mi++) {
            if (A_COL)
                ldsm4t(abase + (uint32_t)(mi * 16 * 2),
                       a[mi][0], a[mi][1], a[mi][2], a[mi][3]);
            else
                ldsm4(abase + (uint32_t)(mi * 16 * PADH * 2),
                      a[mi][0], a[mi][1], a[mi][2], a[mi][3]);
        }
        #pragma unroll
        for (int njp = 0; njp < 2; njp++)
            ldsm4(bbase + (uint32_t)(njp * 16 * PADH * 2),
                  b[2 * njp][0], b[2 * njp][1], b[2 * njp + 1][0], b[2 * njp + 1][1]);
        #pragma unroll
        for (int mi = 0; mi < 4; mi++)
            #pragma unroll
            for (int nj = 0; nj < 4; nj++)
                mma16(acc[mi][nj], a[mi], b[nj]);
    };

    // ---- 3-stage pipeline ----
    issue_stage(0, 0);
    CP_COMMIT();
    if (KT > 1) issue_stage(1, 1);
    CP_COMMIT();
    CP_WAIT1();
    __syncthreads();

    for (int kt = 0; kt < KT; kt++) {
        compute(kt % 3);
        if (kt + 2 < KT) issue_stage((kt + 2) % 3, kt + 2);
        CP_COMMIT();
        CP_WAIT1();
        __syncthreads();
    }

    // ---- epilogue ----
    const int r = lane >> 2, c = lane & 3;
    #pragma unroll
    for (int mi = 0; mi < 4; mi++) {
        int m = m0 + wm * 64 + mi * 16 + r;
        #pragma unroll
        for (int nj = 0; nj < 4; nj++) {
            int j = j0 + wn * 32 + nj * 8 + 2 * c;
            if (j < Nj) {
                float bj0 = HAS_BIAS ? bias[j]     : 0.f;
                float bj1 = HAS_BIAS ? bias[j + 1] : 0.f;
                float v0 = acc[mi][nj][0] + bj0;
                float v1 = acc[mi][nj][1] + bj1;
                float v2 = acc[mi][nj][2] + bj0;
                float v3 = acc[mi][nj][3] + bj1;
                if (OUT_T) {
                    ((float*)out)[(size_t)j * M + m]           = v0;
                    ((float*)out)[(size_t)(j + 1) * M + m]     = v1;
                    ((float*)out)[(size_t)j * M + m + 8]       = v2;
                    ((float*)out)[(size_t)(j + 1) * M + m + 8] = v3;
                } else if (sizeof(TO) == 2) {
                    *(uint32_t*)((__half*)out + (size_t)m * Nj + j)       = f2h2(v0, v1);
                    *(uint32_t*)((__half*)out + (size_t)(m + 8) * Nj + j) = f2h2(v2, v3);
                } else {
                    *(float2*)((float*)out + (size_t)m * Nj + j)       = make_float2(v0, v1);
                    *(float2*)((float*)out + (size_t)(m + 8) * Nj + j) = make_float2(v2, v3);
                }
            }
        }
    }
}

// ---------------------------------------------------------------------------
// Deformable bilinear sampling, fp16 value: one thread = (n, l, g, c8),
// 8 channels per thread (uint4 = 8 halves = 16B per corner load).
// ---------------------------------------------------------------------------
__global__ void __launch_bounds__(256)
samp_h8(const __half* __restrict__ value, const float* __restrict__ om,
        __half* __restrict__ sampled)
{
    int t = blockIdx.x * blockDim.x + threadIdx.x;
    if (t >= NN * LL * GG * 4) return;
    int c8 = (t & 3) * 8;
    int g  = (t >> 2) & (GG - 1);
    int nl = t >> 5;
    int l  = nl & (LL - 1);
    int n  = nl >> 12;
    int yy = l >> 6, xx = l & 63;

    const float*  omp = om + nl * OMC + g * 27;
    const __half* vb  = value + (size_t)n * (LL * CC) + g * 32 + c8;

    float a0 = 0.f, a1 = 0.f, a2 = 0.f, a3 = 0.f;
    float a4 = 0.f, a5 = 0.f, a6 = 0.f, a7 = 0.f;

    #pragma unroll
    for (int k = 0; k < KK; k++) {
        float offy = omp[2 * k];
        float offx = omp[2 * k + 1];
        float msk  = omp[18 + k];
        float py = (float)(yy + k / 3 - 1) + offy;
        float px = (float)(xx + k % 3 - 1) + offx;
        float fy = floorf(py), fx = floorf(px);
        float tyf = py - fy, txf = px - fx;
        int y0 = (int)fy, x0 = (int)fx;

        bool yv0 = (unsigned)y0 < HH;
        bool yv1 = (unsigned)(y0 + 1) < HH;
        bool xv0 = (unsigned)x0 < WW;
        bool xv1 = (unsigned)(x0 + 1) < WW;

        float wy0 = 1.f - tyf, wx0 = 1.f - txf;
        float w00 = msk * wy0 * wx0;
        float w01 = msk * wy0 * txf;
        float w10 = msk * tyf * wx0;
        float w11 = msk * tyf * txf;

        const __half* p = vb + (y0 * WW + x0) * CC;

        #pragma unroll
        for (int cr = 0; cr < 4; cr++) {
            bool ok; const __half* cp; float w;
            if (cr == 0)      { ok = yv0 && xv0; cp = p;                w = w00; }
            else if (cr == 1) { ok = yv0 && xv1; cp = p + CC;           w = w01; }
            else if (cr == 2) { ok = yv1 && xv0; cp = p + WW * CC;      w = w10; }
            else              { ok = yv1 && xv1; cp = p + WW * CC + CC; w = w11; }
            if (ok) {
                uint4 v = *(const uint4*)cp;
                float2 f0 = __half22float2(*(__half2*)&v.x);
                float2 f1 = __half22float2(*(__half2*)&v.y);
                float2 f2 = __half22float2(*(__half2*)&v.z);
                float2 f3 = __half22float2(*(__half2*)&v.w);
                a0 = fmaf(w, f0.x, a0); a1 = fmaf(w, f0.y, a1);
                a2 = fmaf(w, f1.x, a2); a3 = fmaf(w, f1.y, a3);
                a4 = fmaf(w, f2.x, a4); a5 = fmaf(w, f2.y, a5);
                a6 = fmaf(w, f3.x, a6); a7 = fmaf(w, f3.y, a7);
            }
        }
    }

    uint4 o;
    o.x = f2h2(a0, a1); o.y = f2h2(a2, a3);
    o.z = f2h2(a4, a5); o.w = f2h2(a6, a7);
    *(uint4*)(sampled + (size_t)nl * CC + g * 32 + c8) = o;
}

// ---------------------------------------------------------------------------
extern "C" void kernel_launch(void* const* d_in, const int* in_sizes, int n_in,
                              void* d_out, int out_size)
{
    const float* x   = (const float*)d_in[0];
    const float* dww = (const float*)d_in[1];
    const float* dwb = (const float*)d_in[2];
    const float* omw = (const float*)d_in[3];
    const float* omb = (const float*)d_in[4];
    const float* vpw = (const float*)d_in[5];
    const float* vpb = (const float*)d_in[6];
    const float* opw = (const float*)d_in[7];
    float* out = (float*)d_out;

    __half *pxh, *pval, *pomin, *psamp, *pvpw, *pomw, *popw;
    float *pom;
    cudaGetSymbolAddress((void**)&pxh,   g_x_h);
    cudaGetSymbolAddress((void**)&pval,  g_value);
    cudaGetSymbolAddress((void**)&pomin, g_omin);
    cudaGetSymbolAddress((void**)&pom,   g_om);
    cudaGetSymbolAddress((void**)&psamp, g_samp);
    cudaGetSymbolAddress((void**)&pvpw,  g_vpw_h);
    cudaGetSymbolAddress((void**)&pomw,  g_omw_h);
    cudaGetSymbolAddress((void**)&popw,  g_opw_h);

    // 0) pre-halve weights; fused dw conv + x fp16 copy
    prep_w<<<(CC * CC + 255) / 256, 256>>>(vpw, omw, opw);
    dwx_fused<<<(NN * CC * HH * (WW / 4) + 255) / 256, 256>>>(x, dww, dwb);

    // 1) value projection: (n,C,L) x_h -> value (n,L,C) fp16
    gemm_hp<true, false, true, __half>
        <<<dim3(CC / 128, LL / 128, NN), 256>>>(pxh, pvpw, vpb, pval, LL, CC, CC);

    // 2) offset/mask projection: om_in -> om (n,L,216) fp32
    gemm_hp<true, false, true, float>
        <<<dim3((OMC + 127) / 128, LL / 128, NN), 256>>>(pomin, pomw, omb, pom, LL, OMC, CC);

    // 3) deformable sampling -> sampled (n,L,C) fp16
    samp_h8<<<(NN * LL * GG * 4 + 255) / 256, 256>>>(pval, pom, psamp);

    // 4) output projection (half A), write transposed directly to d_out (n,C,H,W)
    gemm_hp<false, true, false, float>
        <<<dim3(CC / 128, LL / 128, NN), 256>>>(psamp, popw, nullptr, out, LL, CC, CC);
}